// round 16
// baseline (speedup 1.0000x reference)
#include <cuda_runtime.h>
#include <cuda_bf16.h>
#include <math.h>
#include <stdint.h>

#define N_NODES 50000
#define IN_CH   256
#define HEADS   3
#define OUT_C   128
#define HC      384
#define NREL    3
#define NEDGE   400000
#define SEMD    128
#define RN      (NREL * N_NODES)     /* 150000 */
#define TOTE    (NREL * NEDGE)       /* 1200000 */
#define XPC     (NREL * HC)          /* 1152 */

/* ------------------------------------------------------------------ */
/* scratch (static device globals — no runtime allocation)             */
/* ------------------------------------------------------------------ */
__device__ float g_xp  [(size_t)N_NODES * XPC];
__device__ float g_gout[(size_t)N_NODES * XPC];
__device__ float g_as  [N_NODES * NREL * HEADS];
__device__ float g_ad  [N_NODES * NREL * HEADS];
__device__ int   g_deg [RN];
__device__ int   g_off [RN + 1];
__device__ int   g_cur [RN];
__device__ int   g_adj [TOTE];
__device__ int   g_part[256];
__device__ int   g_is64;

__device__ __nv_bfloat16 g_xh[(size_t)N_NODES * IN_CH];
__device__ __nv_bfloat16 g_xl[(size_t)N_NODES * IN_CH];
__device__ __nv_bfloat16 g_th[(size_t)XPC * IN_CH];
__device__ __nv_bfloat16 g_tl[(size_t)XPC * IN_CH];
__device__ __nv_bfloat16 g_wh[SEMD * HC];
__device__ __nv_bfloat16 g_wl[SEMD * HC];
__device__ float g_scoreP[2][RN];

__device__ __forceinline__ int load_idx(const void* ei, int is64, size_t pos)
{
    int v = is64 ? (int)((const long long*)ei)[pos]
                 : ((const int*)ei)[pos];
    if ((unsigned)v >= (unsigned)N_NODES) v = 0;
    return v;
}

/* ------------------------------------------------------------------ */
/* init: zero g_deg (all blocks) + edge dtype detection (block 0)      */
/* ------------------------------------------------------------------ */
__global__ void init_kernel(const int* __restrict__ ei32)
{
    if (blockIdx.x == 0 && threadIdx.x == 0) {
        int is64 = 1;
        for (int i = 1; i < 128; i += 2)
            if (ei32[i] != 0) { is64 = 0; break; }
        g_is64 = is64;
    }
    int i = blockIdx.x * blockDim.x + threadIdx.x;
    if (i < RN) g_deg[i] = 0;
}

/* ------------------------------------------------------------------ */
/* prep: count(atomic) || split_x || split_theta || split_wsem         */
/* index-partitioned; count first so its latency hides under splits    */
/* ------------------------------------------------------------------ */
#define NSX (N_NODES * IN_CH)
#define NST (XPC * IN_CH)
#define NSW (SEMD * HC)
#define P1TOT (TOTE + NSX + NST + NSW)

__global__ void prep_kernel(const void* __restrict__ ei,
                            const float* __restrict__ x,
                            const float* __restrict__ theta,
                            const float* __restrict__ W_sem)
{
    int i = blockIdx.x * blockDim.x + threadIdx.x;
    if (i < TOTE) {
        const int is64 = g_is64;
        int r = i / NEDGE;
        int e = i % NEDGE;
        int dst = load_idx(ei, is64, (size_t)r * 2 * NEDGE + NEDGE + e);
        atomicAdd(&g_deg[r * N_NODES + dst], 1);
        return;
    }
    i -= TOTE;
    if (i < NSX) {
        float v = x[i];
        __nv_bfloat16 h = __float2bfloat16(v);
        g_xh[i] = h;
        g_xl[i] = __float2bfloat16(v - __bfloat162float(h));
        return;
    }
    i -= NSX;
    if (i < NST) {
        int j = i / IN_CH;
        int k = i % IN_CH;
        int r  = j / HC;
        int hc = j % HC;
        float v = theta[((size_t)r * IN_CH + k) * HC + hc];
        __nv_bfloat16 h = __float2bfloat16(v);
        g_th[i] = h;
        g_tl[i] = __float2bfloat16(v - __bfloat162float(h));
        return;
    }
    i -= NST;
    if (i < NSW) {
        int s = i / HC;
        int d = i % HC;
        float v = W_sem[(size_t)d * SEMD + s];
        __nv_bfloat16 h = __float2bfloat16(v);
        g_wh[i] = h;
        g_wl[i] = __float2bfloat16(v - __bfloat162float(h));
    }
}

/* ------------------------------------------------------------------ */
/* mma.sync / ldmatrix / cp.async helpers                              */
/* ------------------------------------------------------------------ */
__device__ __forceinline__ void mma16816(float* c, const uint32_t* a,
                                         const uint32_t* b)
{
    asm volatile(
        "mma.sync.aligned.m16n8k16.row.col.f32.bf16.bf16.f32 "
        "{%0,%1,%2,%3}, {%4,%5,%6,%7}, {%8,%9}, {%0,%1,%2,%3};"
        : "+f"(c[0]), "+f"(c[1]), "+f"(c[2]), "+f"(c[3])
        : "r"(a[0]), "r"(a[1]), "r"(a[2]), "r"(a[3]),
          "r"(b[0]), "r"(b[1]));
}

__device__ __forceinline__ void ldsm_x4(uint32_t* r, uint32_t addr)
{
    asm volatile("ldmatrix.sync.aligned.m8n8.x4.shared.b16 {%0,%1,%2,%3}, [%4];"
                 : "=r"(r[0]), "=r"(r[1]), "=r"(r[2]), "=r"(r[3])
                 : "r"(addr));
}

__device__ __forceinline__ uint32_t cvta_s(const void* p)
{
    return (uint32_t)__cvta_generic_to_shared(p);
}

#define CP16(dst, src, sz) \
    asm volatile("cp.async.cg.shared.global [%0], [%1], 16, %2;" \
                 :: "r"(dst), "l"(src), "r"(sz))
#define CP_COMMIT() asm volatile("cp.async.commit_group;")
#define CP_WAIT(n)  asm volatile("cp.async.wait_group %0;" :: "n"(n))

__device__ __forceinline__ uint32_t pack_bf2(float a, float b)
{
    uint32_t lo = (uint32_t)__bfloat16_as_ushort(__float2bfloat16(a));
    uint32_t hi = (uint32_t)__bfloat16_as_ushort(__float2bfloat16(b));
    return (hi << 16) | lo;
}

__device__ __forceinline__ float fast_tanh(float x)
{
    float e = __expf(2.f * x);
    return 1.f - __fdividef(2.f, e + 1.f);
}

/* ------------------------------------------------------------------ */
/* GEMM1 (cp.async double-buffered HMMA, fused asd epilogue)           */
/* + CSR fill fused into low blockIdx.y rows (first wave)              */
/* ------------------------------------------------------------------ */
#define BK    32
#define LDA   40
#define TILE_ELEMS (128 * LDA)
#define BUF_ELEMS  (4 * TILE_ELEMS)
#define GEMM_DSMEM (2 * BUF_ELEMS * 2)

#define FILL_PER_B 1024                       /* 256 thr x 4 edges */
#define FILL_BLOCKS ((TOTE + FILL_PER_B - 1) / FILL_PER_B)  /* 1172 */
#define FILL_ROWS   ((FILL_BLOCKS + 8) / 9)   /* 131 rows of 9    */
#define GEMM_ROWS   ((N_NODES + 127) / 128)   /* 391              */

__global__ __launch_bounds__(256, 2)
void gemm1_mma_kernel(const float* __restrict__ att_src,
                      const float* __restrict__ att_dst,
                      const void* __restrict__ ei)
{
    extern __shared__ __nv_bfloat16 dsm[];
    const int tid = threadIdx.x;

    /* ---- fill part: first-wave blocks ---- */
    if (blockIdx.y < FILL_ROWS) {
        const int b = blockIdx.y * 9 + blockIdx.x;
        const int is64 = g_is64;
#pragma unroll
        for (int u = 0; u < 4; u++) {
            const int i = b * FILL_PER_B + u * 256 + tid;
            if (i < TOTE) {
                const int r = i / NEDGE;
                const int e = i % NEDGE;
                const int src = load_idx(ei, is64, (size_t)r * 2 * NEDGE + e);
                const int dst = load_idx(ei, is64, (size_t)r * 2 * NEDGE + NEDGE + e);
                const int pos = atomicAdd(&g_cur[r * N_NODES + dst], 1);
                if (pos >= 0 && pos < TOTE) g_adj[pos] = src;
            }
        }
        return;
    }

    const int wid   = tid >> 5;
    const int lane  = tid & 31;
    const int wm    = wid & 3;
    const int wn    = wid >> 2;
    const int row0  = (blockIdx.y - FILL_ROWS) * 128;
    const int col0  = blockIdx.x * 128;

    float c[2][8][4];
#pragma unroll
    for (int i = 0; i < 2; i++)
#pragma unroll
        for (int j = 0; j < 8; j++)
#pragma unroll
            for (int q = 0; q < 4; q++) c[i][j][q] = 0.f;

    const int laA_r = lane & 15;
    const int laA_k = (lane >> 4) * 8;
    uint32_t aAH[2], aAL[2];
#pragma unroll
    for (int i = 0; i < 2; i++) {
        const int rr = wm * 32 + i * 16 + laA_r;
        aAH[i] = cvta_s(&dsm[0 * TILE_ELEMS + rr * LDA + laA_k]);
        aAL[i] = cvta_s(&dsm[1 * TILE_ELEMS + rr * LDA + laA_k]);
    }
    const int laB_n = (lane & 7) + ((lane >> 4) << 3);
    const int laB_k = ((lane >> 3) & 1) * 8;
    uint32_t aBH[4], aBL[4];
#pragma unroll
    for (int j2 = 0; j2 < 4; j2++) {
        const int nr = wn * 64 + j2 * 16 + laB_n;
        aBH[j2] = cvta_s(&dsm[2 * TILE_ELEMS + nr * LDA + laB_k]);
        aBL[j2] = cvta_s(&dsm[3 * TILE_ELEMS + nr * LDA + laB_k]);
    }

    const int sr = tid >> 1;
    const int sc = (tid & 1) * 16;
    const int am = row0 + sr;
    const int asz = (am < N_NODES) ? 16 : 0;
    const uint32_t dA = cvta_s(&dsm[sr * LDA + sc]);
    const size_t agi = (size_t)am * IN_CH + sc;
    const size_t bgi = (size_t)(col0 + sr) * IN_CH + sc;

    {
        CP16(dA + 0 * TILE_ELEMS * 2, g_xh + agi, asz);
        CP16(dA + 1 * TILE_ELEMS * 2, g_xl + agi, asz);
        CP16(dA + 2 * TILE_ELEMS * 2, g_th + bgi, 16);
        CP16(dA + 3 * TILE_ELEMS * 2, g_tl + bgi, 16);
        CP16(dA + 0 * TILE_ELEMS * 2 + 16, g_xh + agi + 8, asz);
        CP16(dA + 1 * TILE_ELEMS * 2 + 16, g_xl + agi + 8, asz);
        CP16(dA + 2 * TILE_ELEMS * 2 + 16, g_th + bgi + 8, 16);
        CP16(dA + 3 * TILE_ELEMS * 2 + 16, g_tl + bgi + 8, 16);
        CP_COMMIT();
    }

    int buf = 0;
    for (int kc = 0; kc < IN_CH; kc += BK) {
        __syncthreads();
        const int has_next = (kc + BK < IN_CH);
        if (has_next) {
            const uint32_t dN = dA + (buf ^ 1) * (uint32_t)(BUF_ELEMS * 2);
            const size_t ag = agi + kc + BK;
            const size_t bg = bgi + kc + BK;
            CP16(dN + 0 * TILE_ELEMS * 2, g_xh + ag, asz);
            CP16(dN + 1 * TILE_ELEMS * 2, g_xl + ag, asz);
            CP16(dN + 2 * TILE_ELEMS * 2, g_th + bg, 16);
            CP16(dN + 3 * TILE_ELEMS * 2, g_tl + bg, 16);
            CP16(dN + 0 * TILE_ELEMS * 2 + 16, g_xh + ag + 8, asz);
            CP16(dN + 1 * TILE_ELEMS * 2 + 16, g_xl + ag + 8, asz);
            CP16(dN + 2 * TILE_ELEMS * 2 + 16, g_th + bg + 8, 16);
            CP16(dN + 3 * TILE_ELEMS * 2 + 16, g_tl + bg + 8, 16);
            CP_COMMIT();
            CP_WAIT(1);
        } else {
            CP_WAIT(0);
        }
        __syncthreads();

        const uint32_t boff = buf * (uint32_t)(BUF_ELEMS * 2);
#pragma unroll
        for (int ks = 0; ks < BK; ks += 16) {
            const uint32_t koff = boff + ks * 2;
            uint32_t ah[2][4], al[2][4];
#pragma unroll
            for (int i = 0; i < 2; i++) {
                ldsm_x4(ah[i], aAH[i] + koff);
                ldsm_x4(al[i], aAL[i] + koff);
            }
            uint32_t bh[8][2], bl[8][2];
#pragma unroll
            for (int j2 = 0; j2 < 4; j2++) {
                ldsm_x4(&bh[2 * j2][0], aBH[j2] + koff);
                ldsm_x4(&bl[2 * j2][0], aBL[j2] + koff);
            }
#pragma unroll
            for (int i = 0; i < 2; i++)
#pragma unroll
                for (int j = 0; j < 8; j++) {
                    mma16816(c[i][j], ah[i], bh[j]);
                    mma16816(c[i][j], ah[i], bl[j]);
                    mma16816(c[i][j], al[i], bh[j]);
                }
        }
        buf ^= 1;
    }

    /* ---- epilogue 1: store xp tile ---- */
    const int crow = lane >> 2;
    const int ccol = (lane & 3) * 2;
#pragma unroll
    for (int i = 0; i < 2; i++) {
        const int mbase = row0 + wm * 32 + i * 16;
#pragma unroll
        for (int j = 0; j < 8; j++) {
            const int nbase = col0 + wn * 64 + j * 8 + ccol;
            const int m0 = mbase + crow;
            const int m1 = m0 + 8;
            if (m0 < N_NODES)
                *(float2*)&g_xp[(size_t)m0 * XPC + nbase] =
                    make_float2(c[i][j][0], c[i][j][1]);
            if (m1 < N_NODES)
                *(float2*)&g_xp[(size_t)m1 * XPC + nbase] =
                    make_float2(c[i][j][2], c[i][j][3]);
        }
    }

    /* ---- epilogue 2: fused asd ---- */
    float ds[2][2] = {{0.f, 0.f}, {0.f, 0.f}};
    float dd[2][2] = {{0.f, 0.f}, {0.f, 0.f}};
#pragma unroll
    for (int j = 0; j < 8; j++) {
        const int col = col0 + wn * 64 + j * 8 + ccol;
        const float s0 = att_src[col], s1 = att_src[col + 1];
        const float d0 = att_dst[col], d1 = att_dst[col + 1];
#pragma unroll
        for (int i = 0; i < 2; i++) {
            ds[i][0] += c[i][j][0] * s0 + c[i][j][1] * s1;
            ds[i][1] += c[i][j][2] * s0 + c[i][j][3] * s1;
            dd[i][0] += c[i][j][0] * d0 + c[i][j][1] * d1;
            dd[i][1] += c[i][j][2] * d0 + c[i][j][3] * d1;
        }
    }
#pragma unroll
    for (int o = 1; o <= 2; o <<= 1)
#pragma unroll
        for (int i = 0; i < 2; i++) {
            ds[i][0] += __shfl_xor_sync(0xffffffffu, ds[i][0], o);
            ds[i][1] += __shfl_xor_sync(0xffffffffu, ds[i][1], o);
            dd[i][0] += __shfl_xor_sync(0xffffffffu, dd[i][0], o);
            dd[i][1] += __shfl_xor_sync(0xffffffffu, dd[i][1], o);
        }

    float* sred = (float*)dsm;
    __syncthreads();
    if ((lane & 3) == 0) {
#pragma unroll
        for (int i = 0; i < 2; i++)
#pragma unroll
            for (int h = 0; h < 2; h++) {
                const int rowloc = wm * 32 + i * 16 + h * 8 + crow;
                sred[rowloc * 2 + wn]       = ds[i][h];
                sred[512 + rowloc * 2 + wn] = dd[i][h];
            }
    }
    __syncthreads();
    if (tid < 128) {
        const int n = row0 + tid;
        if (n < N_NODES) {
            const int r = col0 / HC;
            const int h = (col0 % HC) / OUT_C;
            const int o = (n * NREL + r) * HEADS + h;
            g_as[o] = sred[tid * 2] + sred[tid * 2 + 1];
            g_ad[o] = sred[512 + tid * 2] + sred[512 + tid * 2 + 1];
        }
    }
}

/* ------------------------------------------------------------------ */
/* semantic GEMM via mma.sync (ldmatrix fragments), fused tanh epilog  */
/* ------------------------------------------------------------------ */
__global__ __launch_bounds__(256, 2)
void sem_score_kernel(const float* __restrict__ b_sem,
                      const float* __restrict__ q_sem)
{
    __shared__ __nv_bfloat16 sAh[128][LDA];
    __shared__ __nv_bfloat16 sAl[128][LDA];
    __shared__ __nv_bfloat16 sBh[128][LDA];
    __shared__ __nv_bfloat16 sBl[128][LDA];

    const int tid   = threadIdx.x;
    const int wid   = tid >> 5;
    const int lane  = tid & 31;
    const int wm    = wid & 3;
    const int wn    = wid >> 2;
    const int row0  = blockIdx.x * 128;

    float c[2][8][4];
#pragma unroll
    for (int i = 0; i < 2; i++)
#pragma unroll
        for (int j = 0; j < 8; j++)
#pragma unroll
            for (int q = 0; q < 4; q++) c[i][j][q] = 0.f;

    const int laA_r = lane & 15;
    const int laA_k = (lane >> 4) * 8;
    uint32_t aAH[2], aAL[2];
#pragma unroll
    for (int i = 0; i < 2; i++) {
        const int rr = wm * 32 + i * 16 + laA_r;
        aAH[i] = cvta_s(&sAh[rr][laA_k]);
        aAL[i] = cvta_s(&sAl[rr][laA_k]);
    }
    const int laB_n = (lane & 7) + ((lane >> 4) << 3);
    const int laB_k = ((lane >> 3) & 1) * 8;
    uint32_t aBH[4], aBL[4];
#pragma unroll
    for (int j2 = 0; j2 < 4; j2++) {
        const int nr = wn * 64 + j2 * 16 + laB_n;
        aBH[j2] = cvta_s(&sBh[nr][laB_k]);
        aBL[j2] = cvta_s(&sBl[nr][laB_k]);
    }

    const int sr = tid >> 1;
    const int sc = (tid & 1) * 16;

    for (int kc = 0; kc < HC; kc += BK) {
        __syncthreads();
        {
            const int m = row0 + sr;
#pragma unroll
            for (int t = 0; t < 4; t++) {
                float4 v = make_float4(0.f, 0.f, 0.f, 0.f);
                if (m < RN)
                    v = *(const float4*)&g_gout[(size_t)m * HC + kc + sc + t * 4];
                float hx = __bfloat162float(__float2bfloat16(v.x));
                float hy = __bfloat162float(__float2bfloat16(v.y));
                float hz = __bfloat162float(__float2bfloat16(v.z));
                float hw = __bfloat162float(__float2bfloat16(v.w));
                *(uint32_t*)&sAh[sr][sc + t * 4]     = pack_bf2(v.x, v.y);
                *(uint32_t*)&sAh[sr][sc + t * 4 + 2] = pack_bf2(v.z, v.w);
                *(uint32_t*)&sAl[sr][sc + t * 4]     = pack_bf2(v.x - hx, v.y - hy);
                *(uint32_t*)&sAl[sr][sc + t * 4 + 2] = pack_bf2(v.z - hz, v.w - hw);
            }
            const size_t bgi = ((size_t)sr * HC + kc + sc) >> 3;
            *(uint4*)&sBh[sr][sc]     = ((const uint4*)g_wh)[bgi];
            *(uint4*)&sBl[sr][sc]     = ((const uint4*)g_wl)[bgi];
            *(uint4*)&sBh[sr][sc + 8] = ((const uint4*)g_wh)[bgi + 1];
            *(uint4*)&sBl[sr][sc + 8] = ((const uint4*)g_wl)[bgi + 1];
        }
        __syncthreads();

#pragma unroll
        for (int ks = 0; ks < BK; ks += 16) {
            const uint32_t koff = ks * 2;
            uint32_t ah[2][4], al[2][4];
#pragma unroll
            for (int i = 0; i < 2; i++) {
                ldsm_x4(ah[i], aAH[i] + koff);
                ldsm_x4(al[i], aAL[i] + koff);
            }
            uint32_t bh[8][2], bl[8][2];
#pragma unroll
            for (int j2 = 0; j2 < 4; j2++) {
                ldsm_x4(&bh[2 * j2][0], aBH[j2] + koff);
                ldsm_x4(&bl[2 * j2][0], aBL[j2] + koff);
            }
#pragma unroll
            for (int i = 0; i < 2; i++)
#pragma unroll
                for (int j = 0; j < 8; j++) {
                    mma16816(c[i][j], ah[i], bh[j]);
                    mma16816(c[i][j], ah[i], bl[j]);
                    mma16816(c[i][j], al[i], bh[j]);
                }
        }
    }

    const int crow = lane >> 2;
    const int ccol = (lane & 3) * 2;
    float rs[2][2] = {{0.f, 0.f}, {0.f, 0.f}};
#pragma unroll
    for (int i = 0; i < 2; i++)
#pragma unroll
        for (int j = 0; j < 8; j++) {
            const int col = wn * 64 + j * 8 + ccol;
            const float b0 = b_sem[col],     b1 = b_sem[col + 1];
            const float q0 = q_sem[col],     q1 = q_sem[col + 1];
            rs[i][0] += fast_tanh(c[i][j][0] + b0) * q0
                      + fast_tanh(c[i][j][1] + b1) * q1;
            rs[i][1] += fast_tanh(c[i][j][2] + b0) * q0
                      + fast_tanh(c[i][j][3] + b1) * q1;
        }
#pragma unroll
    for (int o = 1; o <= 2; o <<= 1) {
#pragma unroll
        for (int i = 0; i < 2; i++) {
            rs[i][0] += __shfl_xor_sync(0xffffffffu, rs[i][0], o);
            rs[i][1] += __shfl_xor_sync(0xffffffffu, rs[i][1], o);
        }
    }
    if ((lane & 3) == 0) {
#pragma unroll
        for (int i = 0; i < 2; i++)
#pragma unroll
            for (int h = 0; h < 2; h++) {
                const int row = row0 + wm * 32 + i * 16 + h * 8 + crow;
                if (row < RN) g_scoreP[wn][row] = rs[i][h];
            }
    }
}

/* ------------------------------------------------------------------ */
/* sem_final: softmax over 3 relation scores + weighted combine        */
/* ------------------------------------------------------------------ */
__global__ void sem_final_kernel(const float* __restrict__ mgx,
                                 const float* __restrict__ gsrc,
                                 const float* __restrict__ gdst,
                                 float* __restrict__ out)
{
    const int node = blockIdx.x * 4 + (threadIdx.x >> 5);
    const int lane = threadIdx.x & 31;
    if (node >= N_NODES) return;

    const int rb = node * NREL;
    const float S0 = g_scoreP[0][rb + 0] + g_scoreP[1][rb + 0];
    const float S1 = g_scoreP[0][rb + 1] + g_scoreP[1][rb + 1];
    const float S2 = g_scoreP[0][rb + 2] + g_scoreP[1][rb + 2];

    const float bm = fmaxf(S0, fmaxf(S1, S2));
    const float e0 = expf(S0 - bm), e1 = expf(S1 - bm), e2 = expf(S2 - bm);
    const float iv = 1.f / (e0 + e1 + e2);
    const float b0 = e0 * iv, b1 = e1 * iv, b2 = e2 * iv;

    const float* gp = &g_gout[(size_t)node * XPC];
#pragma unroll
    for (int t = 0; t < 3; t++) {
        const int cidx = lane * 4 + t * 128;
        float4 v0 = *(const float4*)&gp[cidx];
        float4 v1 = *(const float4*)&gp[HC + cidx];
        float4 v2 = *(const float4*)&gp[2 * HC + cidx];
        float4 mg = *(const float4*)&mgx[cidx];
        float4 gs = *(const float4*)&gsrc[cidx];
        float4 gd = *(const float4*)&gdst[cidx];
        float4 o;
        o.x = b0 * v0.x + b1 * v1.x + b2 * v2.x + mg.x * (gs.x + gd.x);
        o.y = b0 * v0.y + b1 * v1.y + b2 * v2.y + mg.y * (gs.y + gd.y);
        o.z = b0 * v0.z + b1 * v1.z + b2 * v2.z + mg.z * (gs.z + gd.z);
        o.w = b0 * v0.w + b1 * v1.w + b2 * v2.w + mg.w * (gs.w + gd.w);
        *(float4*)&out[(size_t)node * HC + cidx] = o;
    }
}

/* ------------------------------------------------------------------ */
/* CSR scans                                                           */
/* ------------------------------------------------------------------ */
#define SCH 1024
__global__ void scan1_kernel()
{
    __shared__ int s[256];
    const int b = blockIdx.x, t = threadIdx.x;
    const int base = b * SCH + t * 4;
    int v[4], sum = 0;
#pragma unroll
    for (int i = 0; i < 4; i++) {
        int idx = base + i;
        v[i] = (idx < RN) ? g_deg[idx] : 0;
        sum += v[i];
    }
    s[t] = sum;
    __syncthreads();
    for (int o = 1; o < 256; o <<= 1) {
        int xv = (t >= o) ? s[t - o] : 0;
        __syncthreads();
        s[t] += xv;
        __syncthreads();
    }
    int run = s[t] - sum;
    if (t == 255) g_part[b] = s[t];
#pragma unroll
    for (int i = 0; i < 4; i++) {
        int idx = base + i;
        if (idx < RN) g_off[idx] = run;
        run += v[i];
    }
}

__global__ void scan2_kernel(int nb)
{
    __shared__ int s[256];
    const int t = threadIdx.x;
    int v = (t < nb) ? g_part[t] : 0;
    s[t] = v;
    __syncthreads();
    for (int o = 1; o < 256; o <<= 1) {
        int xv = (t >= o) ? s[t - o] : 0;
        __syncthreads();
        s[t] += xv;
        __syncthreads();
    }
    g_part[t] = s[t] - v;
}

__global__ void scan3_kernel()
{
    int i = blockIdx.x * blockDim.x + threadIdx.x;
    if (i < RN) {
        int v = g_off[i] + g_part[i / SCH];
        g_off[i] = v;
        g_cur[i] = v;
    }
    if (i == 0) g_off[RN] = TOTE;
}

/* ------------------------------------------------------------------ */
/* GAT aggregation                                                     */
/* ------------------------------------------------------------------ */
#define ACAP 64
__device__ __forceinline__ float lrelu(float v) { return v > 0.f ? v : 0.2f * v; }

__global__ void agg_kernel(const float* __restrict__ gat_bias)
{
    __shared__ float pbuf[4][ACAP][3];
    __shared__ int   sbuf[4][ACAP];

    const int w    = threadIdx.x >> 5;
    const int lane = threadIdx.x & 31;
    const int item = blockIdx.x * 4 + w;
    if (item >= RN) return;
    const int r = item / N_NODES;
    const int n = item % N_NODES;

    const int off0 = g_off[r * N_NODES + n];
    const int deg  = g_off[r * N_NODES + n + 1] - off0;
    const int tot  = deg + 1;

    const float ad0 = g_ad[(n * NREL + r) * HEADS + 0];
    const float ad1 = g_ad[(n * NREL + r) * HEADS + 1];
    const float ad2 = g_ad[(n * NREL + r) * HEADS + 2];

    float4 acc[3];
#pragma unroll
    for (int k = 0; k < 3; k++) acc[k] = make_float4(0.f, 0.f, 0.f, 0.f);
    float z0 = 0.f, z1 = 0.f, z2 = 0.f;

    if (tot <= ACAP) {
        for (int i = lane; i < tot; i += 32) {
            const int src = (i < deg) ? g_adj[off0 + i] : n;
            sbuf[w][i] = src;
            const float* as = &g_as[(src * NREL + r) * HEADS];
            pbuf[w][i][0] = lrelu(as[0] + ad0);
            pbuf[w][i][1] = lrelu(as[1] + ad1);
            pbuf[w][i][2] = lrelu(as[2] + ad2);
        }
        __syncwarp();
        float m0 = -1e30f, m1 = -1e30f, m2 = -1e30f;
        for (int i = lane; i < tot; i += 32) {
            m0 = fmaxf(m0, pbuf[w][i][0]);
            m1 = fmaxf(m1, pbuf[w][i][1]);
            m2 = fmaxf(m2, pbuf[w][i][2]);
        }
#pragma unroll
        for (int o = 16; o > 0; o >>= 1) {
            m0 = fmaxf(m0, __shfl_xor_sync(0xffffffffu, m0, o));
            m1 = fmaxf(m1, __shfl_xor_sync(0xffffffffu, m1, o));
            m2 = fmaxf(m2, __shfl_xor_sync(0xffffffffu, m2, o));
        }
        for (int i = lane; i < tot; i += 32) {
            const float p0 = expf(pbuf[w][i][0] - m0);
            const float p1 = expf(pbuf[w][i][1] - m1);
            const float p2 = expf(pbuf[w][i][2] - m2);
            pbuf[w][i][0] = p0;  z0 += p0;
            pbuf[w][i][1] = p1;  z1 += p1;
            pbuf[w][i][2] = p2;  z2 += p2;
        }
#pragma unroll
        for (int o = 16; o > 0; o >>= 1) {
            z0 += __shfl_xor_sync(0xffffffffu, z0, o);
            z1 += __shfl_xor_sync(0xffffffffu, z1, o);
            z2 += __shfl_xor_sync(0xffffffffu, z2, o);
        }
        __syncwarp();
        for (int j = 0; j < tot; j++) {
            const int   src = sbuf[w][j];
            const float a0  = pbuf[w][j][0];
            const float a1  = pbuf[w][j][1];
            const float a2  = pbuf[w][j][2];
            const float4* xr = (const float4*)&g_xp[(size_t)src * XPC + r * HC];
            const float4 x0 = xr[lane];
            const float4 x1 = xr[lane + 32];
            const float4 x2 = xr[lane + 64];
            acc[0].x = fmaf(a0, x0.x, acc[0].x);
            acc[0].y = fmaf(a0, x0.y, acc[0].y);
            acc[0].z = fmaf(a0, x0.z, acc[0].z);
            acc[0].w = fmaf(a0, x0.w, acc[0].w);
            acc[1].x = fmaf(a1, x1.x, acc[1].x);
            acc[1].y = fmaf(a1, x1.y, acc[1].y);
            acc[1].z = fmaf(a1, x1.z, acc[1].z);
            acc[1].w = fmaf(a1, x1.w, acc[1].w);
            acc[2].x = fmaf(a2, x2.x, acc[2].x);
            acc[2].y = fmaf(a2, x2.y, acc[2].y);
            acc[2].z = fmaf(a2, x2.z, acc[2].z);
            acc[2].w = fmaf(a2, x2.w, acc[2].w);
        }
    } else {
        float m0 = -1e30f, m1 = -1e30f, m2 = -1e30f;
        for (int base = 0; base < tot; base += 32) {
            const int i = base + lane;
            if (i < tot) {
                const int src = (i < deg) ? g_adj[off0 + i] : n;
                const float* as = &g_as[(src * NREL + r) * HEADS];
                m0 = fmaxf(m0, lrelu(as[0] + ad0));
                m1 = fmaxf(m1, lrelu(as[1] + ad1));
                m2 = fmaxf(m2, lrelu(as[2] + ad2));
            }
        }
#pragma unroll
        for (int o = 16; o > 0; o >>= 1) {
            m0 = fmaxf(m0, __shfl_xor_sync(0xffffffffu, m0, o));
            m1 = fmaxf(m1, __shfl_xor_sync(0xffffffffu, m1, o));
            m2 = fmaxf(m2, __shfl_xor_sync(0xffffffffu, m2, o));
        }
        for (int c0 = 0; c0 < tot; c0 += ACAP) {
            const int clen = min(ACAP, tot - c0);
            for (int base = 0; base < clen; base += 32) {
                const int i = base + lane;
                if (i < clen) {
                    const int gi  = c0 + i;
                    const int src = (gi < deg) ? g_adj[off0 + gi] : n;
                    sbuf[w][i] = src;
                    const float* as = &g_as[(src * NREL + r) * HEADS];
                    const float p0 = expf(lrelu(as[0] + ad0) - m0);
                    const float p1 = expf(lrelu(as[1] + ad1) - m1);
                    const float p2 = expf(lrelu(as[2] + ad2) - m2);
                    pbuf[w][i][0] = p0;  z0 += p0;
                    pbuf[w][i][1] = p1;  z1 += p1;
                    pbuf[w][i][2] = p2;  z2 += p2;
                }
            }
            __syncwarp();
            for (int j = 0; j < clen; j++) {
                const int   src = sbuf[w][j];
                const float a0  = pbuf[w][j][0];
                const float a1  = pbuf[w][j][1];
                const float a2  = pbuf[w][j][2];
                const float4* xr = (const float4*)&g_xp[(size_t)src * XPC + r * HC];
                const float4 x0 = xr[lane];
                const float4 x1 = xr[lane + 32];
                const float4 x2 = xr[lane + 64];
                acc[0].x = fmaf(a0, x0.x, acc[0].x);
                acc[0].y = fmaf(a0, x0.y, acc[0].y);
                acc[0].z = fmaf(a0, x0.z, acc[0].z);
                acc[0].w = fmaf(a0, x0.w, acc[0].w);
                acc[1].x = fmaf(a1, x1.x, acc[1].x);
                acc[1].y = fmaf(a1, x1.y, acc[1].y);
                acc[1].z = fmaf(a1, x1.z, acc[1].z);
                acc[1].w = fmaf(a1, x1.w, acc[1].w);
                acc[2].x = fmaf(a2, x2.x, acc[2].x);
                acc[2].y = fmaf(a2, x2.y, acc[2].y);
                acc[2].z = fmaf(a2, x2.z, acc[2].z);
                acc[2].w = fmaf(a2, x2.w, acc[2].w);
            }
            __syncwarp();
        }
#pragma unroll
        for (int o = 16; o > 0; o >>= 1) {
            z0 += __shfl_xor_sync(0xffffffffu, z0, o);
            z1 += __shfl_xor_sync(0xffffffffu, z1, o);
            z2 += __shfl_xor_sync(0xffffffffu, z2, o);
        }
    }

    const float iv0 = 1.f / (z0 + 1e-16f);
    const float iv1 = 1.f / (z1 + 1e-16f);
    const float iv2 = 1.f / (z2 + 1e-16f);

    const float4* bp4 = (const float4*)&gat_bias[r * HC];
    float4* op4 = (float4*)&g_gout[((size_t)n * NREL + r) * HC];
    const float ivs[3] = {iv0, iv1, iv2};
#pragma unroll
    for (int k = 0; k < 3; k++) {
        const float4 b = bp4[lane + 32 * k];
        float4 v;
        v.x = fmaxf(fmaf(acc[k].x, ivs[k], b.x), 0.f);
        v.y = fmaxf(fmaf(acc[k].y, ivs[k], b.y), 0.f);
        v.z = fmaxf(fmaf(acc[k].z, ivs[k], b.z), 0.f);
        v.w = fmaxf(fmaf(acc[k].w, ivs[k], b.w), 0.f);
        op4[lane + 32 * k] = v;
    }
}

/* ------------------------------------------------------------------ */
extern "C" void kernel_launch(void* const* d_in, const int* in_sizes, int n_in,
                              void* d_out, int out_size)
{
    const float* x        = (const float*)d_in[0];
    const float* theta    = (const float*)d_in[1];
    const float* att_src  = (const float*)d_in[2];
    const float* att_dst  = (const float*)d_in[3];
    const float* gat_bias = (const float*)d_in[4];
    const float* W_sem    = (const float*)d_in[5];
    const float* b_sem    = (const float*)d_in[6];
    const float* q_sem    = (const float*)d_in[7];
    const float* mgx      = (const float*)d_in[8];
    const float* gsrc     = (const float*)d_in[9];
    const float* gdst     = (const float*)d_in[10];
    const void*  ei       = d_in[11];
    float* out = (float*)d_out;

    /* 0. init: zero g_deg + dtype detection */
    init_kernel<<<(RN + 255) / 256, 256>>>((const int*)ei);

    /* 1. fused prep: CSR count || bf16 splits */
    prep_kernel<<<(P1TOT + 255) / 256, 256>>>(ei, x, theta, W_sem);

    /* 2. CSR offset scans */
    scan1_kernel<<<(RN + SCH - 1) / SCH, 256>>>();
    scan2_kernel<<<1, 256>>>((RN + SCH - 1) / SCH);
    scan3_kernel<<<(RN + 255) / 256, 256>>>();

    /* 3. fused: CSR fill (first-wave blocks) + HMMA GEMM1 (+asd) */
    cudaFuncSetAttribute(gemm1_mma_kernel,
                         cudaFuncAttributeMaxDynamicSharedMemorySize, GEMM_DSMEM);
    gemm1_mma_kernel<<<dim3(9, FILL_ROWS + GEMM_ROWS), 256, GEMM_DSMEM>>>(
        att_src, att_dst, ei);

    /* 4. per-(relation,node) GAT softmax + aggregate */
    agg_kernel<<<RN / 4, 128>>>(gat_bias);

    /* 5. semantic attention: HMMA score GEMM + softmax combine */
    sem_score_kernel<<<(RN + 127) / 128, 256>>>(b_sem, q_sem);
    sem_final_kernel<<<(N_NODES + 3) / 4, 128>>>(mgx, gsrc, gdst, out);
}

// round 17
// speedup vs baseline: 1.0733x; 1.0733x over previous
#include <cuda_runtime.h>
#include <cuda_bf16.h>
#include <cuda_fp16.h>
#include <math.h>
#include <stdint.h>

#define N_NODES 50000
#define IN_CH   256
#define HEADS   3
#define OUT_C   128
#define HC      384
#define NREL    3
#define NEDGE   400000
#define SEMD    128
#define RN      (NREL * N_NODES)     /* 150000 */
#define TOTE    (NREL * NEDGE)       /* 1200000 */
#define XPC     (NREL * HC)          /* 1152 */

/* ------------------------------------------------------------------ */
/* scratch (static device globals — no runtime allocation)             */
/* ------------------------------------------------------------------ */
__device__ __half g_xph[(size_t)N_NODES * XPC];   /* xp, fp16 (agg-only) */
__device__ float g_gout[(size_t)N_NODES * XPC];
__device__ float g_as  [N_NODES * NREL * HEADS];
__device__ float g_ad  [N_NODES * NREL * HEADS];
__device__ int   g_deg [RN];
__device__ int   g_off [RN + 1];
__device__ int   g_cur [RN];
__device__ int   g_adj [TOTE];
__device__ int   g_part[256];
__device__ int   g_is64;

__device__ __nv_bfloat16 g_xh[(size_t)N_NODES * IN_CH];
__device__ __nv_bfloat16 g_xl[(size_t)N_NODES * IN_CH];
__device__ __nv_bfloat16 g_th[(size_t)XPC * IN_CH];
__device__ __nv_bfloat16 g_tl[(size_t)XPC * IN_CH];
__device__ __nv_bfloat16 g_wh[SEMD * HC];
__device__ __nv_bfloat16 g_wl[SEMD * HC];
__device__ float g_scoreP[2][RN];

__device__ __forceinline__ int load_idx(const void* ei, int is64, size_t pos)
{
    int v = is64 ? (int)((const long long*)ei)[pos]
                 : ((const int*)ei)[pos];
    if ((unsigned)v >= (unsigned)N_NODES) v = 0;
    return v;
}

/* ------------------------------------------------------------------ */
/* init: zero g_deg (all blocks) + edge dtype detection (block 0)      */
/* ------------------------------------------------------------------ */
__global__ void init_kernel(const int* __restrict__ ei32)
{
    if (blockIdx.x == 0 && threadIdx.x == 0) {
        int is64 = 1;
        for (int i = 1; i < 128; i += 2)
            if (ei32[i] != 0) { is64 = 0; break; }
        g_is64 = is64;
    }
    int i = blockIdx.x * blockDim.x + threadIdx.x;
    if (i < RN) g_deg[i] = 0;
}

/* ------------------------------------------------------------------ */
/* prep: count(atomic) || split_x || split_theta || split_wsem         */
/* ------------------------------------------------------------------ */
#define NSX (N_NODES * IN_CH)
#define NST (XPC * IN_CH)
#define NSW (SEMD * HC)
#define P1TOT (TOTE + NSX + NST + NSW)

__global__ void prep_kernel(const void* __restrict__ ei,
                            const float* __restrict__ x,
                            const float* __restrict__ theta,
                            const float* __restrict__ W_sem)
{
    int i = blockIdx.x * blockDim.x + threadIdx.x;
    if (i < TOTE) {
        const int is64 = g_is64;
        int r = i / NEDGE;
        int e = i % NEDGE;
        int dst = load_idx(ei, is64, (size_t)r * 2 * NEDGE + NEDGE + e);
        atomicAdd(&g_deg[r * N_NODES + dst], 1);
        return;
    }
    i -= TOTE;
    if (i < NSX) {
        float v = x[i];
        __nv_bfloat16 h = __float2bfloat16(v);
        g_xh[i] = h;
        g_xl[i] = __float2bfloat16(v - __bfloat162float(h));
        return;
    }
    i -= NSX;
    if (i < NST) {
        int j = i / IN_CH;
        int k = i % IN_CH;
        int r  = j / HC;
        int hc = j % HC;
        float v = theta[((size_t)r * IN_CH + k) * HC + hc];
        __nv_bfloat16 h = __float2bfloat16(v);
        g_th[i] = h;
        g_tl[i] = __float2bfloat16(v - __bfloat162float(h));
        return;
    }
    i -= NST;
    if (i < NSW) {
        int s = i / HC;
        int d = i % HC;
        float v = W_sem[(size_t)d * SEMD + s];
        __nv_bfloat16 h = __float2bfloat16(v);
        g_wh[i] = h;
        g_wl[i] = __float2bfloat16(v - __bfloat162float(h));
    }
}

/* ------------------------------------------------------------------ */
/* mma.sync / ldmatrix / cp.async helpers                              */
/* ------------------------------------------------------------------ */
__device__ __forceinline__ void mma16816(float* c, const uint32_t* a,
                                         const uint32_t* b)
{
    asm volatile(
        "mma.sync.aligned.m16n8k16.row.col.f32.bf16.bf16.f32 "
        "{%0,%1,%2,%3}, {%4,%5,%6,%7}, {%8,%9}, {%0,%1,%2,%3};"
        : "+f"(c[0]), "+f"(c[1]), "+f"(c[2]), "+f"(c[3])
        : "r"(a[0]), "r"(a[1]), "r"(a[2]), "r"(a[3]),
          "r"(b[0]), "r"(b[1]));
}

__device__ __forceinline__ void ldsm_x4(uint32_t* r, uint32_t addr)
{
    asm volatile("ldmatrix.sync.aligned.m8n8.x4.shared.b16 {%0,%1,%2,%3}, [%4];"
                 : "=r"(r[0]), "=r"(r[1]), "=r"(r[2]), "=r"(r[3])
                 : "r"(addr));
}

__device__ __forceinline__ uint32_t cvta_s(const void* p)
{
    return (uint32_t)__cvta_generic_to_shared(p);
}

#define CP16(dst, src, sz) \
    asm volatile("cp.async.cg.shared.global [%0], [%1], 16, %2;" \
                 :: "r"(dst), "l"(src), "r"(sz))
#define CP_COMMIT() asm volatile("cp.async.commit_group;")
#define CP_WAIT(n)  asm volatile("cp.async.wait_group %0;" :: "n"(n))

__device__ __forceinline__ uint32_t pack_bf2(float a, float b)
{
    uint32_t lo = (uint32_t)__bfloat16_as_ushort(__float2bfloat16(a));
    uint32_t hi = (uint32_t)__bfloat16_as_ushort(__float2bfloat16(b));
    return (hi << 16) | lo;
}

__device__ __forceinline__ float fast_tanh(float x)
{
    float e = __expf(2.f * x);
    return 1.f - __fdividef(2.f, e + 1.f);
}

/* ------------------------------------------------------------------ */
/* GEMM1 (cp.async double-buffered HMMA, fused asd epilogue)           */
/* + CSR fill fused into low blockIdx.y rows                           */
/* ------------------------------------------------------------------ */
#define BK    32
#define LDA   40
#define TILE_ELEMS (128 * LDA)
#define BUF_ELEMS  (4 * TILE_ELEMS)
#define GEMM_DSMEM (2 * BUF_ELEMS * 2)

#define FILL_PER_B 1024
#define FILL_BLOCKS ((TOTE + FILL_PER_B - 1) / FILL_PER_B)
#define FILL_ROWS   ((FILL_BLOCKS + 8) / 9)
#define GEMM_ROWS   ((N_NODES + 127) / 128)

__global__ __launch_bounds__(256, 2)
void gemm1_mma_kernel(const float* __restrict__ att_src,
                      const float* __restrict__ att_dst,
                      const void* __restrict__ ei)
{
    extern __shared__ __nv_bfloat16 dsm[];
    const int tid = threadIdx.x;

    if (blockIdx.y < FILL_ROWS) {
        const int b = blockIdx.y * 9 + blockIdx.x;
        const int is64 = g_is64;
#pragma unroll
        for (int u = 0; u < 4; u++) {
            const int i = b * FILL_PER_B + u * 256 + tid;
            if (i < TOTE) {
                const int r = i / NEDGE;
                const int e = i % NEDGE;
                const int src = load_idx(ei, is64, (size_t)r * 2 * NEDGE + e);
                const int dst = load_idx(ei, is64, (size_t)r * 2 * NEDGE + NEDGE + e);
                const int pos = atomicAdd(&g_cur[r * N_NODES + dst], 1);
                if (pos >= 0 && pos < TOTE) g_adj[pos] = src;
            }
        }
        return;
    }

    const int wid   = tid >> 5;
    const int lane  = tid & 31;
    const int wm    = wid & 3;
    const int wn    = wid >> 2;
    const int row0  = (blockIdx.y - FILL_ROWS) * 128;
    const int col0  = blockIdx.x * 128;

    float c[2][8][4];
#pragma unroll
    for (int i = 0; i < 2; i++)
#pragma unroll
        for (int j = 0; j < 8; j++)
#pragma unroll
            for (int q = 0; q < 4; q++) c[i][j][q] = 0.f;

    const int laA_r = lane & 15;
    const int laA_k = (lane >> 4) * 8;
    uint32_t aAH[2], aAL[2];
#pragma unroll
    for (int i = 0; i < 2; i++) {
        const int rr = wm * 32 + i * 16 + laA_r;
        aAH[i] = cvta_s(&dsm[0 * TILE_ELEMS + rr * LDA + laA_k]);
        aAL[i] = cvta_s(&dsm[1 * TILE_ELEMS + rr * LDA + laA_k]);
    }
    const int laB_n = (lane & 7) + ((lane >> 4) << 3);
    const int laB_k = ((lane >> 3) & 1) * 8;
    uint32_t aBH[4], aBL[4];
#pragma unroll
    for (int j2 = 0; j2 < 4; j2++) {
        const int nr = wn * 64 + j2 * 16 + laB_n;
        aBH[j2] = cvta_s(&dsm[2 * TILE_ELEMS + nr * LDA + laB_k]);
        aBL[j2] = cvta_s(&dsm[3 * TILE_ELEMS + nr * LDA + laB_k]);
    }

    const int sr = tid >> 1;
    const int sc = (tid & 1) * 16;
    const int am = row0 + sr;
    const int asz = (am < N_NODES) ? 16 : 0;
    const uint32_t dA = cvta_s(&dsm[sr * LDA + sc]);
    const size_t agi = (size_t)am * IN_CH + sc;
    const size_t bgi = (size_t)(col0 + sr) * IN_CH + sc;

    {
        CP16(dA + 0 * TILE_ELEMS * 2, g_xh + agi, asz);
        CP16(dA + 1 * TILE_ELEMS * 2, g_xl + agi, asz);
        CP16(dA + 2 * TILE_ELEMS * 2, g_th + bgi, 16);
        CP16(dA + 3 * TILE_ELEMS * 2, g_tl + bgi, 16);
        CP16(dA + 0 * TILE_ELEMS * 2 + 16, g_xh + agi + 8, asz);
        CP16(dA + 1 * TILE_ELEMS * 2 + 16, g_xl + agi + 8, asz);
        CP16(dA + 2 * TILE_ELEMS * 2 + 16, g_th + bgi + 8, 16);
        CP16(dA + 3 * TILE_ELEMS * 2 + 16, g_tl + bgi + 8, 16);
        CP_COMMIT();
    }

    int buf = 0;
    for (int kc = 0; kc < IN_CH; kc += BK) {
        __syncthreads();
        const int has_next = (kc + BK < IN_CH);
        if (has_next) {
            const uint32_t dN = dA + (buf ^ 1) * (uint32_t)(BUF_ELEMS * 2);
            const size_t ag = agi + kc + BK;
            const size_t bg = bgi + kc + BK;
            CP16(dN + 0 * TILE_ELEMS * 2, g_xh + ag, asz);
            CP16(dN + 1 * TILE_ELEMS * 2, g_xl + ag, asz);
            CP16(dN + 2 * TILE_ELEMS * 2, g_th + bg, 16);
            CP16(dN + 3 * TILE_ELEMS * 2, g_tl + bg, 16);
            CP16(dN + 0 * TILE_ELEMS * 2 + 16, g_xh + ag + 8, asz);
            CP16(dN + 1 * TILE_ELEMS * 2 + 16, g_xl + ag + 8, asz);
            CP16(dN + 2 * TILE_ELEMS * 2 + 16, g_th + bg + 8, 16);
            CP16(dN + 3 * TILE_ELEMS * 2 + 16, g_tl + bg + 8, 16);
            CP_COMMIT();
            CP_WAIT(1);
        } else {
            CP_WAIT(0);
        }
        __syncthreads();

        const uint32_t boff = buf * (uint32_t)(BUF_ELEMS * 2);
#pragma unroll
        for (int ks = 0; ks < BK; ks += 16) {
            const uint32_t koff = boff + ks * 2;
            uint32_t ah[2][4], al[2][4];
#pragma unroll
            for (int i = 0; i < 2; i++) {
                ldsm_x4(ah[i], aAH[i] + koff);
                ldsm_x4(al[i], aAL[i] + koff);
            }
            uint32_t bh[8][2], bl[8][2];
#pragma unroll
            for (int j2 = 0; j2 < 4; j2++) {
                ldsm_x4(&bh[2 * j2][0], aBH[j2] + koff);
                ldsm_x4(&bl[2 * j2][0], aBL[j2] + koff);
            }
#pragma unroll
            for (int i = 0; i < 2; i++)
#pragma unroll
                for (int j = 0; j < 8; j++) {
                    mma16816(c[i][j], ah[i], bh[j]);
                    mma16816(c[i][j], ah[i], bl[j]);
                    mma16816(c[i][j], al[i], bh[j]);
                }
        }
        buf ^= 1;
    }

    /* ---- epilogue 1: store xp tile as fp16 ---- */
    const int crow = lane >> 2;
    const int ccol = (lane & 3) * 2;
#pragma unroll
    for (int i = 0; i < 2; i++) {
        const int mbase = row0 + wm * 32 + i * 16;
#pragma unroll
        for (int j = 0; j < 8; j++) {
            const int nbase = col0 + wn * 64 + j * 8 + ccol;
            const int m0 = mbase + crow;
            const int m1 = m0 + 8;
            if (m0 < N_NODES)
                *(__half2*)&g_xph[(size_t)m0 * XPC + nbase] =
                    __floats2half2_rn(c[i][j][0], c[i][j][1]);
            if (m1 < N_NODES)
                *(__half2*)&g_xph[(size_t)m1 * XPC + nbase] =
                    __floats2half2_rn(c[i][j][2], c[i][j][3]);
        }
    }

    /* ---- epilogue 2: fused asd (fp32 accumulators) ---- */
    float ds[2][2] = {{0.f, 0.f}, {0.f, 0.f}};
    float dd[2][2] = {{0.f, 0.f}, {0.f, 0.f}};
#pragma unroll
    for (int j = 0; j < 8; j++) {
        const int col = col0 + wn * 64 + j * 8 + ccol;
        const float s0 = att_src[col], s1 = att_src[col + 1];
        const float d0 = att_dst[col], d1 = att_dst[col + 1];
#pragma unroll
        for (int i = 0; i < 2; i++) {
            ds[i][0] += c[i][j][0] * s0 + c[i][j][1] * s1;
            ds[i][1] += c[i][j][2] * s0 + c[i][j][3] * s1;
            dd[i][0] += c[i][j][0] * d0 + c[i][j][1] * d1;
            dd[i][1] += c[i][j][2] * d0 + c[i][j][3] * d1;
        }
    }
#pragma unroll
    for (int o = 1; o <= 2; o <<= 1)
#pragma unroll
        for (int i = 0; i < 2; i++) {
            ds[i][0] += __shfl_xor_sync(0xffffffffu, ds[i][0], o);
            ds[i][1] += __shfl_xor_sync(0xffffffffu, ds[i][1], o);
            dd[i][0] += __shfl_xor_sync(0xffffffffu, dd[i][0], o);
            dd[i][1] += __shfl_xor_sync(0xffffffffu, dd[i][1], o);
        }

    float* sred = (float*)dsm;
    __syncthreads();
    if ((lane & 3) == 0) {
#pragma unroll
        for (int i = 0; i < 2; i++)
#pragma unroll
            for (int h = 0; h < 2; h++) {
                const int rowloc = wm * 32 + i * 16 + h * 8 + crow;
                sred[rowloc * 2 + wn]       = ds[i][h];
                sred[512 + rowloc * 2 + wn] = dd[i][h];
            }
    }
    __syncthreads();
    if (tid < 128) {
        const int n = row0 + tid;
        if (n < N_NODES) {
            const int r = col0 / HC;
            const int h = (col0 % HC) / OUT_C;
            const int o = (n * NREL + r) * HEADS + h;
            g_as[o] = sred[tid * 2] + sred[tid * 2 + 1];
            g_ad[o] = sred[512 + tid * 2] + sred[512 + tid * 2 + 1];
        }
    }
}

/* ------------------------------------------------------------------ */
/* semantic GEMM via mma.sync (ldmatrix fragments), fused tanh epilog  */
/* ------------------------------------------------------------------ */
__global__ __launch_bounds__(256, 2)
void sem_score_kernel(const float* __restrict__ b_sem,
                      const float* __restrict__ q_sem)
{
    __shared__ __nv_bfloat16 sAh[128][LDA];
    __shared__ __nv_bfloat16 sAl[128][LDA];
    __shared__ __nv_bfloat16 sBh[128][LDA];
    __shared__ __nv_bfloat16 sBl[128][LDA];

    const int tid   = threadIdx.x;
    const int wid   = tid >> 5;
    const int lane  = tid & 31;
    const int wm    = wid & 3;
    const int wn    = wid >> 2;
    const int row0  = blockIdx.x * 128;

    float c[2][8][4];
#pragma unroll
    for (int i = 0; i < 2; i++)
#pragma unroll
        for (int j = 0; j < 8; j++)
#pragma unroll
            for (int q = 0; q < 4; q++) c[i][j][q] = 0.f;

    const int laA_r = lane & 15;
    const int laA_k = (lane >> 4) * 8;
    uint32_t aAH[2], aAL[2];
#pragma unroll
    for (int i = 0; i < 2; i++) {
        const int rr = wm * 32 + i * 16 + laA_r;
        aAH[i] = cvta_s(&sAh[rr][laA_k]);
        aAL[i] = cvta_s(&sAl[rr][laA_k]);
    }
    const int laB_n = (lane & 7) + ((lane >> 4) << 3);
    const int laB_k = ((lane >> 3) & 1) * 8;
    uint32_t aBH[4], aBL[4];
#pragma unroll
    for (int j2 = 0; j2 < 4; j2++) {
        const int nr = wn * 64 + j2 * 16 + laB_n;
        aBH[j2] = cvta_s(&sBh[nr][laB_k]);
        aBL[j2] = cvta_s(&sBl[nr][laB_k]);
    }

    const int sr = tid >> 1;
    const int sc = (tid & 1) * 16;

    for (int kc = 0; kc < HC; kc += BK) {
        __syncthreads();
        {
            const int m = row0 + sr;
#pragma unroll
            for (int t = 0; t < 4; t++) {
                float4 v = make_float4(0.f, 0.f, 0.f, 0.f);
                if (m < RN)
                    v = *(const float4*)&g_gout[(size_t)m * HC + kc + sc + t * 4];
                float hx = __bfloat162float(__float2bfloat16(v.x));
                float hy = __bfloat162float(__float2bfloat16(v.y));
                float hz = __bfloat162float(__float2bfloat16(v.z));
                float hw = __bfloat162float(__float2bfloat16(v.w));
                *(uint32_t*)&sAh[sr][sc + t * 4]     = pack_bf2(v.x, v.y);
                *(uint32_t*)&sAh[sr][sc + t * 4 + 2] = pack_bf2(v.z, v.w);
                *(uint32_t*)&sAl[sr][sc + t * 4]     = pack_bf2(v.x - hx, v.y - hy);
                *(uint32_t*)&sAl[sr][sc + t * 4 + 2] = pack_bf2(v.z - hz, v.w - hw);
            }
            const size_t bgi = ((size_t)sr * HC + kc + sc) >> 3;
            *(uint4*)&sBh[sr][sc]     = ((const uint4*)g_wh)[bgi];
            *(uint4*)&sBl[sr][sc]     = ((const uint4*)g_wl)[bgi];
            *(uint4*)&sBh[sr][sc + 8] = ((const uint4*)g_wh)[bgi + 1];
            *(uint4*)&sBl[sr][sc + 8] = ((const uint4*)g_wl)[bgi + 1];
        }
        __syncthreads();

#pragma unroll
        for (int ks = 0; ks < BK; ks += 16) {
            const uint32_t koff = ks * 2;
            uint32_t ah[2][4], al[2][4];
#pragma unroll
            for (int i = 0; i < 2; i++) {
                ldsm_x4(ah[i], aAH[i] + koff);
                ldsm_x4(al[i], aAL[i] + koff);
            }
            uint32_t bh[8][2], bl[8][2];
#pragma unroll
            for (int j2 = 0; j2 < 4; j2++) {
                ldsm_x4(&bh[2 * j2][0], aBH[j2] + koff);
                ldsm_x4(&bl[2 * j2][0], aBL[j2] + koff);
            }
#pragma unroll
            for (int i = 0; i < 2; i++)
#pragma unroll
                for (int j = 0; j < 8; j++) {
                    mma16816(c[i][j], ah[i], bh[j]);
                    mma16816(c[i][j], ah[i], bl[j]);
                    mma16816(c[i][j], al[i], bh[j]);
                }
        }
    }

    const int crow = lane >> 2;
    const int ccol = (lane & 3) * 2;
    float rs[2][2] = {{0.f, 0.f}, {0.f, 0.f}};
#pragma unroll
    for (int i = 0; i < 2; i++)
#pragma unroll
        for (int j = 0; j < 8; j++) {
            const int col = wn * 64 + j * 8 + ccol;
            const float b0 = b_sem[col],     b1 = b_sem[col + 1];
            const float q0 = q_sem[col],     q1 = q_sem[col + 1];
            rs[i][0] += fast_tanh(c[i][j][0] + b0) * q0
                      + fast_tanh(c[i][j][1] + b1) * q1;
            rs[i][1] += fast_tanh(c[i][j][2] + b0) * q0
                      + fast_tanh(c[i][j][3] + b1) * q1;
        }
#pragma unroll
    for (int o = 1; o <= 2; o <<= 1) {
#pragma unroll
        for (int i = 0; i < 2; i++) {
            rs[i][0] += __shfl_xor_sync(0xffffffffu, rs[i][0], o);
            rs[i][1] += __shfl_xor_sync(0xffffffffu, rs[i][1], o);
        }
    }
    if ((lane & 3) == 0) {
#pragma unroll
        for (int i = 0; i < 2; i++)
#pragma unroll
            for (int h = 0; h < 2; h++) {
                const int row = row0 + wm * 32 + i * 16 + h * 8 + crow;
                if (row < RN) g_scoreP[wn][row] = rs[i][h];
            }
    }
}

/* ------------------------------------------------------------------ */
/* sem_final: softmax over 3 relation scores + weighted combine        */
/* ------------------------------------------------------------------ */
__global__ void sem_final_kernel(const float* __restrict__ mgx,
                                 const float* __restrict__ gsrc,
                                 const float* __restrict__ gdst,
                                 float* __restrict__ out)
{
    const int node = blockIdx.x * 4 + (threadIdx.x >> 5);
    const int lane = threadIdx.x & 31;
    if (node >= N_NODES) return;

    const int rb = node * NREL;
    const float S0 = g_scoreP[0][rb + 0] + g_scoreP[1][rb + 0];
    const float S1 = g_scoreP[0][rb + 1] + g_scoreP[1][rb + 1];
    const float S2 = g_scoreP[0][rb + 2] + g_scoreP[1][rb + 2];

    const float bm = fmaxf(S0, fmaxf(S1, S2));
    const float e0 = expf(S0 - bm), e1 = expf(S1 - bm), e2 = expf(S2 - bm);
    const float iv = 1.f / (e0 + e1 + e2);
    const float b0 = e0 * iv, b1 = e1 * iv, b2 = e2 * iv;

    const float* gp = &g_gout[(size_t)node * XPC];
#pragma unroll
    for (int t = 0; t < 3; t++) {
        const int cidx = lane * 4 + t * 128;
        float4 v0 = *(const float4*)&gp[cidx];
        float4 v1 = *(const float4*)&gp[HC + cidx];
        float4 v2 = *(const float4*)&gp[2 * HC + cidx];
        float4 mg = *(const float4*)&mgx[cidx];
        float4 gs = *(const float4*)&gsrc[cidx];
        float4 gd = *(const float4*)&gdst[cidx];
        float4 o;
        o.x = b0 * v0.x + b1 * v1.x + b2 * v2.x + mg.x * (gs.x + gd.x);
        o.y = b0 * v0.y + b1 * v1.y + b2 * v2.y + mg.y * (gs.y + gd.y);
        o.z = b0 * v0.z + b1 * v1.z + b2 * v2.z + mg.z * (gs.z + gd.z);
        o.w = b0 * v0.w + b1 * v1.w + b2 * v2.w + mg.w * (gs.w + gd.w);
        *(float4*)&out[(size_t)node * HC + cidx] = o;
    }
}

/* ------------------------------------------------------------------ */
/* CSR scans                                                           */
/* ------------------------------------------------------------------ */
#define SCH 1024
__global__ void scan1_kernel()
{
    __shared__ int s[256];
    const int b = blockIdx.x, t = threadIdx.x;
    const int base = b * SCH + t * 4;
    int v[4], sum = 0;
#pragma unroll
    for (int i = 0; i < 4; i++) {
        int idx = base + i;
        v[i] = (idx < RN) ? g_deg[idx] : 0;
        sum += v[i];
    }
    s[t] = sum;
    __syncthreads();
    for (int o = 1; o < 256; o <<= 1) {
        int xv = (t >= o) ? s[t - o] : 0;
        __syncthreads();
        s[t] += xv;
        __syncthreads();
    }
    int run = s[t] - sum;
    if (t == 255) g_part[b] = s[t];
#pragma unroll
    for (int i = 0; i < 4; i++) {
        int idx = base + i;
        if (idx < RN) g_off[idx] = run;
        run += v[i];
    }
}

__global__ void scan2_kernel(int nb)
{
    __shared__ int s[256];
    const int t = threadIdx.x;
    int v = (t < nb) ? g_part[t] : 0;
    s[t] = v;
    __syncthreads();
    for (int o = 1; o < 256; o <<= 1) {
        int xv = (t >= o) ? s[t - o] : 0;
        __syncthreads();
        s[t] += xv;
        __syncthreads();
    }
    g_part[t] = s[t] - v;
}

__global__ void scan3_kernel()
{
    int i = blockIdx.x * blockDim.x + threadIdx.x;
    if (i < RN) {
        int v = g_off[i] + g_part[i / SCH];
        g_off[i] = v;
        g_cur[i] = v;
    }
    if (i == 0) g_off[RN] = TOTE;
}

/* ------------------------------------------------------------------ */
/* GAT aggregation (fp16 xp gather)                                    */
/* ------------------------------------------------------------------ */
#define ACAP 64
__device__ __forceinline__ float lrelu(float v) { return v > 0.f ? v : 0.2f * v; }

__device__ __forceinline__ void gather_fma(float4* acc, const float* a,
                                           const __half* xr, int lane)
{
#pragma unroll
    for (int k = 0; k < 3; k++) {
        const uint2 raw = *(const uint2*)&xr[k * 128 + lane * 4];
        const float2 f01 = __half22float2(*(const __half2*)&raw.x);
        const float2 f23 = __half22float2(*(const __half2*)&raw.y);
        acc[k].x = fmaf(a[k], f01.x, acc[k].x);
        acc[k].y = fmaf(a[k], f01.y, acc[k].y);
        acc[k].z = fmaf(a[k], f23.x, acc[k].z);
        acc[k].w = fmaf(a[k], f23.y, acc[k].w);
    }
}

__global__ void agg_kernel(const float* __restrict__ gat_bias)
{
    __shared__ float pbuf[4][ACAP][3];
    __shared__ int   sbuf[4][ACAP];

    const int w    = threadIdx.x >> 5;
    const int lane = threadIdx.x & 31;
    const int item = blockIdx.x * 4 + w;
    if (item >= RN) return;
    const int r = item / N_NODES;
    const int n = item % N_NODES;

    const int off0 = g_off[r * N_NODES + n];
    const int deg  = g_off[r * N_NODES + n + 1] - off0;
    const int tot  = deg + 1;

    const float ad0 = g_ad[(n * NREL + r) * HEADS + 0];
    const float ad1 = g_ad[(n * NREL + r) * HEADS + 1];
    const float ad2 = g_ad[(n * NREL + r) * HEADS + 2];

    float4 acc[3];
#pragma unroll
    for (int k = 0; k < 3; k++) acc[k] = make_float4(0.f, 0.f, 0.f, 0.f);
    float z0 = 0.f, z1 = 0.f, z2 = 0.f;

    if (tot <= ACAP) {
        for (int i = lane; i < tot; i += 32) {
            const int src = (i < deg) ? g_adj[off0 + i] : n;
            sbuf[w][i] = src;
            const float* as = &g_as[(src * NREL + r) * HEADS];
            pbuf[w][i][0] = lrelu(as[0] + ad0);
            pbuf[w][i][1] = lrelu(as[1] + ad1);
            pbuf[w][i][2] = lrelu(as[2] + ad2);
        }
        __syncwarp();
        float m0 = -1e30f, m1 = -1e30f, m2 = -1e30f;
        for (int i = lane; i < tot; i += 32) {
            m0 = fmaxf(m0, pbuf[w][i][0]);
            m1 = fmaxf(m1, pbuf[w][i][1]);
            m2 = fmaxf(m2, pbuf[w][i][2]);
        }
#pragma unroll
        for (int o = 16; o > 0; o >>= 1) {
            m0 = fmaxf(m0, __shfl_xor_sync(0xffffffffu, m0, o));
            m1 = fmaxf(m1, __shfl_xor_sync(0xffffffffu, m1, o));
            m2 = fmaxf(m2, __shfl_xor_sync(0xffffffffu, m2, o));
        }
        for (int i = lane; i < tot; i += 32) {
            const float p0 = expf(pbuf[w][i][0] - m0);
            const float p1 = expf(pbuf[w][i][1] - m1);
            const float p2 = expf(pbuf[w][i][2] - m2);
            pbuf[w][i][0] = p0;  z0 += p0;
            pbuf[w][i][1] = p1;  z1 += p1;
            pbuf[w][i][2] = p2;  z2 += p2;
        }
#pragma unroll
        for (int o = 16; o > 0; o >>= 1) {
            z0 += __shfl_xor_sync(0xffffffffu, z0, o);
            z1 += __shfl_xor_sync(0xffffffffu, z1, o);
            z2 += __shfl_xor_sync(0xffffffffu, z2, o);
        }
        __syncwarp();
        for (int j = 0; j < tot; j++) {
            const int src = sbuf[w][j];
            gather_fma(acc, pbuf[w][j],
                       &g_xph[(size_t)src * XPC + r * HC], lane);
        }
    } else {
        float m0 = -1e30f, m1 = -1e30f, m2 = -1e30f;
        for (int base = 0; base < tot; base += 32) {
            const int i = base + lane;
            if (i < tot) {
                const int src = (i < deg) ? g_adj[off0 + i] : n;
                const float* as = &g_as[(src * NREL + r) * HEADS];
                m0 = fmaxf(m0, lrelu(as[0] + ad0));
                m1 = fmaxf(m1, lrelu(as[1] + ad1));
                m2 = fmaxf(m2, lrelu(as[2] + ad2));
            }
        }
#pragma unroll
        for (int o = 16; o > 0; o >>= 1) {
            m0 = fmaxf(m0, __shfl_xor_sync(0xffffffffu, m0, o));
            m1 = fmaxf(m1, __shfl_xor_sync(0xffffffffu, m1, o));
            m2 = fmaxf(m2, __shfl_xor_sync(0xffffffffu, m2, o));
        }
        for (int c0 = 0; c0 < tot; c0 += ACAP) {
            const int clen = min(ACAP, tot - c0);
            for (int base = 0; base < clen; base += 32) {
                const int i = base + lane;
                if (i < clen) {
                    const int gi  = c0 + i;
                    const int src = (gi < deg) ? g_adj[off0 + gi] : n;
                    sbuf[w][i] = src;
                    const float* as = &g_as[(src * NREL + r) * HEADS];
                    const float p0 = expf(lrelu(as[0] + ad0) - m0);
                    const float p1 = expf(lrelu(as[1] + ad1) - m1);
                    const float p2 = expf(lrelu(as[2] + ad2) - m2);
                    pbuf[w][i][0] = p0;  z0 += p0;
                    pbuf[w][i][1] = p1;  z1 += p1;
                    pbuf[w][i][2] = p2;  z2 += p2;
                }
            }
            __syncwarp();
            for (int j = 0; j < clen; j++) {
                const int src = sbuf[w][j];
                gather_fma(acc, pbuf[w][j],
                           &g_xph[(size_t)src * XPC + r * HC], lane);
            }
            __syncwarp();
        }
#pragma unroll
        for (int o = 16; o > 0; o >>= 1) {
            z0 += __shfl_xor_sync(0xffffffffu, z0, o);
            z1 += __shfl_xor_sync(0xffffffffu, z1, o);
            z2 += __shfl_xor_sync(0xffffffffu, z2, o);
        }
    }

    const float iv0 = 1.f / (z0 + 1e-16f);
    const float iv1 = 1.f / (z1 + 1e-16f);
    const float iv2 = 1.f / (z2 + 1e-16f);

    const float* bp = &gat_bias[r * HC];
    float* op = &g_gout[((size_t)n * NREL + r) * HC];
    const float ivs[3] = {iv0, iv1, iv2};
#pragma unroll
    for (int k = 0; k < 3; k++) {
        const int c = lane * 4 + 128 * k;
        const float4 b = *(const float4*)&bp[c];
        float4 v;
        v.x = fmaxf(fmaf(acc[k].x, ivs[k], b.x), 0.f);
        v.y = fmaxf(fmaf(acc[k].y, ivs[k], b.y), 0.f);
        v.z = fmaxf(fmaf(acc[k].z, ivs[k], b.z), 0.f);
        v.w = fmaxf(fmaf(acc[k].w, ivs[k], b.w), 0.f);
        *(float4*)&op[c] = v;
    }
}

/* ------------------------------------------------------------------ */
extern "C" void kernel_launch(void* const* d_in, const int* in_sizes, int n_in,
                              void* d_out, int out_size)
{
    const float* x        = (const float*)d_in[0];
    const float* theta    = (const float*)d_in[1];
    const float* att_src  = (const float*)d_in[2];
    const float* att_dst  = (const float*)d_in[3];
    const float* gat_bias = (const float*)d_in[4];
    const float* W_sem    = (const float*)d_in[5];
    const float* b_sem    = (const float*)d_in[6];
    const float* q_sem    = (const float*)d_in[7];
    const float* mgx      = (const float*)d_in[8];
    const float* gsrc     = (const float*)d_in[9];
    const float* gdst     = (const float*)d_in[10];
    const void*  ei       = d_in[11];
    float* out = (float*)d_out;

    /* 0. init: zero g_deg + dtype detection */
    init_kernel<<<(RN + 255) / 256, 256>>>((const int*)ei);

    /* 1. fused prep: CSR count || bf16 splits */
    prep_kernel<<<(P1TOT + 255) / 256, 256>>>(ei, x, theta, W_sem);

    /* 2. CSR offset scans */
    scan1_kernel<<<(RN + SCH - 1) / SCH, 256>>>();
    scan2_kernel<<<1, 256>>>((RN + SCH - 1) / SCH);
    scan3_kernel<<<(RN + 255) / 256, 256>>>();

    /* 3. fused: CSR fill (first-wave blocks) + HMMA GEMM1 (+asd) */
    cudaFuncSetAttribute(gemm1_mma_kernel,
                         cudaFuncAttributeMaxDynamicSharedMemorySize, GEMM_DSMEM);
    gemm1_mma_kernel<<<dim3(9, FILL_ROWS + GEMM_ROWS), 256, GEMM_DSMEM>>>(
        att_src, att_dst, ei);

    /* 4. per-(relation,node) GAT softmax + aggregate */
    agg_kernel<<<RN / 4, 128>>>(gat_bias);

    /* 5. semantic attention: HMMA score GEMM + softmax combine */
    sem_score_kernel<<<(RN + 127) / 128, 256>>>(b_sem, q_sem);
    sem_final_kernel<<<(N_NODES + 3) / 4, 128>>>(mgx, gsrc, gdst, out);
}